// round 4
// baseline (speedup 1.0000x reference)
#include <cuda_runtime.h>

#define N_NODES 100000
#define N_EDGES 50000
#define NNZ     3200000
#define D       32
#define ALPHA   0.5f
#define OMA     0.5f   /* 1 - ALPHA */

// ---------------- device scratch (no allocs allowed) ----------------
__device__ __align__(256) float g_X1[N_NODES * D];   // X @ W1 + b1
__device__ __align__(256) float g_Ye[N_EDGES * D];   // Xe @ M2 per hyperedge
__device__ __align__(256) float g_T [N_NODES * D];   // node-level closed-form part
__device__ int   g_deg [N_NODES];                    // incidence count per vertex
__device__ int   g_voff[N_NODES + 1];                // CSR offsets by vertex
__device__ int   g_cur [N_NODES];                    // running cursors for counting sort
__device__ int   g_vedge[NNZ];                       // edge id per incidence, grouped by vertex
__device__ int   g_start[N_EDGES + 1];               // CSR bounds of sorted `edges`
__device__ float g_M1[D * D];                        // W2a @ W_w
__device__ float g_M2[D * D];                        // W2b @ W_w
__device__ float g_c1[D];                            // W2_b @ W_w

// ---------------- init: zero counters + fold small matrices ----------------
__global__ void k_init(const float* __restrict__ W2w,
                       const float* __restrict__ W2b,
                       const float* __restrict__ Ww) {
    int tid = blockIdx.x * blockDim.x + threadIdx.x;
    int stride = gridDim.x * blockDim.x;
    const int total = N_NODES + (N_EDGES + 1);
    for (int i = tid; i < total; i += stride) {
        if (i < N_NODES) g_deg[i] = 0;
        else             g_start[i - N_NODES] = NNZ;
    }
    if (tid < D * D) {
        int k = tid >> 5, j = tid & 31;
        float s1 = 0.f, s2 = 0.f;
        #pragma unroll
        for (int m = 0; m < D; m++) {
            s1 = fmaf(W2w[k * D + m],       Ww[m * D + j], s1);
            s2 = fmaf(W2w[(D + k) * D + m], Ww[m * D + j], s2);
        }
        g_M1[tid] = s1;
        g_M2[tid] = s2;
        if (k == 0) {
            float c = 0.f;
            #pragma unroll
            for (int m = 0; m < D; m++) c = fmaf(W2b[m], Ww[m * D + j], c);
            g_c1[j] = c;
        }
    }
}

// ---------------- edge segment bounds (edges is sorted ascending) ----------------
__global__ void k_fill(const int* __restrict__ edges) {
    int tid = blockIdx.x * blockDim.x + threadIdx.x;
    int stride = gridDim.x * blockDim.x;
    for (int i = tid; i < NNZ; i += stride) {
        int e = edges[i];
        int p = (i == 0) ? -1 : edges[i - 1];
        if (e != p)
            for (int k = p + 1; k <= e; k++) g_start[k] = i;
    }
}

// ---------------- vertex degree histogram ----------------
__global__ void k_deg(const int* __restrict__ vertex) {
    int tid = blockIdx.x * blockDim.x + threadIdx.x;
    int stride = gridDim.x * blockDim.x;
    for (int i = tid; i < NNZ; i += stride)
        atomicAdd(&g_deg[vertex[i]], 1);
}

// ---------------- single-block exclusive prefix sum of degrees ----------------
__global__ void k_scan() {
    __shared__ int ssum[1024];
    const int T = 1024;
    const int per = (N_NODES + T - 1) / T;   // 98
    int t = threadIdx.x;
    int beg = t * per;
    int end = beg + per; if (end > N_NODES) end = N_NODES;
    int s = 0;
    for (int i = beg; i < end; i++) s += g_deg[i];
    ssum[t] = s;
    __syncthreads();
    // Hillis-Steele inclusive scan
    for (int off = 1; off < T; off <<= 1) {
        int v = (t >= off) ? ssum[t - off] : 0;
        __syncthreads();
        ssum[t] += v;
        __syncthreads();
    }
    int run = (t > 0) ? ssum[t - 1] : 0;
    for (int i = beg; i < end; i++) {
        g_voff[i] = run;
        g_cur[i]  = run;
        run += g_deg[i];
    }
    if (t == T - 1) g_voff[N_NODES] = NNZ;
}

// ---------------- counting sort: group incidence edge-ids by vertex ----------------
__global__ void k_sidx(const int* __restrict__ vertex,
                       const int* __restrict__ edges) {
    int tid = blockIdx.x * blockDim.x + threadIdx.x;
    int stride = gridDim.x * blockDim.x;
    for (int i = tid; i < NNZ; i += stride) {
        int v = vertex[i];
        int p = atomicAdd(&g_cur[v], 1);
        g_vedge[p] = edges[i];
    }
}

// ---------------- thread-per-node register matvecs:
//   g_X1 = X @ W1 + b1
//   g_T  = (1-a)*deg*(X@M1 + c1) + a*(X0@Ww) + Wb   (closed-form node part)
__global__ void __launch_bounds__(256) k_pre(
        const float* __restrict__ X,
        const float* __restrict__ X0,
        const float* __restrict__ W1w,
        const float* __restrict__ W1b,
        const float* __restrict__ Ww,
        const float* __restrict__ Wb) {
    __shared__ float sW1[D * D], sM1[D * D], sW[D * D];
    __shared__ float sb1[D], sc1[D], sWb[D];
    int t = threadIdx.x;
    for (int i = t; i < D * D; i += blockDim.x) {
        sW1[i] = W1w[i];
        sM1[i] = g_M1[i];
        sW [i] = Ww[i];
    }
    if (t < D) { sb1[t] = W1b[t]; sc1[t] = g_c1[t]; sWb[t] = Wb[t]; }
    __syncthreads();

    int v = blockIdx.x * blockDim.x + t;
    if (v >= N_NODES) return;

    float x[D];
    const float4* Xr = reinterpret_cast<const float4*>(X) + v * (D / 4);
    #pragma unroll
    for (int i = 0; i < D / 4; i++) {
        float4 q = __ldg(&Xr[i]);
        x[4*i] = q.x; x[4*i+1] = q.y; x[4*i+2] = q.z; x[4*i+3] = q.w;
    }

    float acc[D];
    // phase 1: X1 = x @ W1 + b1
    #pragma unroll
    for (int j = 0; j < D; j++) acc[j] = sb1[j];
    #pragma unroll
    for (int k = 0; k < D; k++) {
        float xk = x[k];
        #pragma unroll
        for (int j = 0; j < D; j++) acc[j] = fmaf(xk, sW1[k * D + j], acc[j]);
    }
    float4* X1r = reinterpret_cast<float4*>(g_X1) + v * (D / 4);
    #pragma unroll
    for (int i = 0; i < D / 4; i++)
        X1r[i] = make_float4(acc[4*i], acc[4*i+1], acc[4*i+2], acc[4*i+3]);

    // phase 2: m = x @ M1 + c1 ; acc := (OMA*deg*m + Wb) / ALPHA
    float degf = __int2float_rn(g_deg[v]);
    float sc = OMA * degf;
    #pragma unroll
    for (int j = 0; j < D; j++) acc[j] = sc1[j];
    #pragma unroll
    for (int k = 0; k < D; k++) {
        float xk = x[k];
        #pragma unroll
        for (int j = 0; j < D; j++) acc[j] = fmaf(xk, sM1[k * D + j], acc[j]);
    }
    #pragma unroll
    for (int j = 0; j < D; j++)
        acc[j] = (fmaf(sc, acc[j], sWb[j])) * (1.0f / ALPHA);

    // phase 3: acc += X0 @ Ww ; T = ALPHA * acc
    const float4* X0r = reinterpret_cast<const float4*>(X0) + v * (D / 4);
    #pragma unroll
    for (int i = 0; i < D / 4; i++) {
        float4 q = __ldg(&X0r[i]);
        x[4*i] = q.x; x[4*i+1] = q.y; x[4*i+2] = q.z; x[4*i+3] = q.w;
    }
    #pragma unroll
    for (int k = 0; k < D; k++) {
        float xk = x[k];
        #pragma unroll
        for (int j = 0; j < D; j++) acc[j] = fmaf(xk, sW[k * D + j], acc[j]);
    }
    float4* Tr = reinterpret_cast<float4*>(g_T) + v * (D / 4);
    #pragma unroll
    for (int i = 0; i < D / 4; i++)
        Tr[i] = make_float4(ALPHA * acc[4*i], ALPHA * acc[4*i+1],
                            ALPHA * acc[4*i+2], ALPHA * acc[4*i+3]);
}

// ---------------- warp-per-edge: Xe = sum(atts * X1[vertex]) over sorted segment,
//                  then Ye = Xe @ M2 (shfl matvec), store. ----------------
__global__ void k_xe(const int* __restrict__ vertex,
                     const float* __restrict__ atts) {
    __shared__ float sM2[D * D];
    int t = threadIdx.x;
    for (int i = t; i < D * D; i += blockDim.x) sM2[i] = g_M2[i];
    __syncthreads();

    int lane = t & 31;
    int warp = (blockIdx.x * blockDim.x + t) >> 5;
    int nwarps = (gridDim.x * blockDim.x) >> 5;

    for (int e = warp; e < N_EDGES; e += nwarps) {
        int s = g_start[e];
        int tEnd = g_start[e + 1];
        if (s >= tEnd) continue;

        float acc = 0.f;
        for (int base = s; base < tEnd; base += 32) {
            int n = tEnd - base; if (n > 32) n = 32;
            int vi = 0; float ai = 0.f;
            if (lane < n) {
                vi = __ldg(&vertex[base + lane]);
                ai = __ldg(&atts[base + lane]);
            }
            #pragma unroll 4
            for (int j = 0; j < n; j++) {
                int   v = __shfl_sync(0xffffffffu, vi, j);
                float a = __shfl_sync(0xffffffffu, ai, j);
                acc = fmaf(a, g_X1[v * D + lane], acc);  // coalesced 128B, L2-resident
            }
        }
        // Ye = acc(row) @ M2 via shfl matvec (lane = out column)
        float y = 0.f;
        #pragma unroll
        for (int k = 0; k < D; k++)
            y = fmaf(__shfl_sync(0xffffffffu, acc, k), sM2[k * D + lane], y);
        g_Ye[e * D + lane] = y;
    }
}

// ---------------- warp-per-vertex: out = T + (1-a) * sum(Ye[incident edges]) ----
__global__ void k_gout(float* __restrict__ out) {
    int t = threadIdx.x;
    int lane = t & 31;
    int warp = (blockIdx.x * blockDim.x + t) >> 5;
    int nwarps = (gridDim.x * blockDim.x) >> 5;

    for (int v = warp; v < N_NODES; v += nwarps) {
        int s = g_voff[v];
        int e2 = g_voff[v + 1];
        float acc = 0.f;
        for (int base = s; base < e2; base += 32) {
            int n = e2 - base; if (n > 32) n = 32;
            int ei = 0;
            if (lane < n) ei = __ldg(&g_vedge[base + lane]);
            #pragma unroll 4
            for (int j = 0; j < n; j++) {
                int ee = __shfl_sync(0xffffffffu, ei, j);
                acc += g_Ye[ee * D + lane];               // coalesced 128B, L2-resident
            }
        }
        out[v * D + lane] = g_T[v * D + lane] + OMA * acc;
    }
}

// ---------------- launch ----------------
extern "C" void kernel_launch(void* const* d_in, const int* in_sizes, int n_in,
                              void* d_out, int out_size) {
    const float* X    = (const float*)d_in[0];
    const float* X0   = (const float*)d_in[1];
    const float* atts = (const float*)d_in[2];
    const float* W1w  = (const float*)d_in[3];
    const float* W1b  = (const float*)d_in[4];
    const float* W2w  = (const float*)d_in[5];
    const float* W2b  = (const float*)d_in[6];
    const float* Ww   = (const float*)d_in[7];
    const float* Wb   = (const float*)d_in[8];
    const int* vertex = (const int*)d_in[9];
    const int* edges  = (const int*)d_in[10];
    float* out = (float*)d_out;

    k_init<<<512, 256>>>(W2w, W2b, Ww);
    k_fill<<<2048, 256>>>(edges);
    k_deg <<<2048, 256>>>(vertex);
    k_scan<<<1, 1024>>>();
    k_sidx<<<2048, 256>>>(vertex, edges);
    k_pre <<<(N_NODES + 255) / 256, 256>>>(X, X0, W1w, W1b, Ww, Wb);
    k_xe  <<<6250, 256>>>(vertex, atts);   // 50k warps = 1 warp / hyperedge
    k_gout<<<6250, 256>>>(out);            // grid-stride, 2 vertices / warp
}

// round 7
// speedup vs baseline: 1.9161x; 1.9161x over previous
#include <cuda_runtime.h>

#define N_NODES 100000
#define N_EDGES 50000
#define NNZ     3200000
#define D       32
#define ALPHA   0.5f
#define OMA     0.5f   /* 1 - ALPHA */

#define N4       (N_NODES / 4)                 /* 25000 int4 */
#define NB_SCAN  ((N4 + 255) / 256)            /* 98 blocks */

// ---------------- device scratch (no allocs allowed) ----------------
__device__ __align__(256) float g_X1[N_NODES * D];   // X @ W1 + b1
__device__ __align__(256) float g_Ye[N_EDGES * D];   // Xe @ M2 per hyperedge
__device__ __align__(256) float g_T [N_NODES * D];   // node-level closed-form part
__device__ __align__(16) int   g_deg [N_NODES];      // incidence count per vertex
__device__ __align__(16) int   g_voff[N_NODES + 4];  // CSR offsets by vertex
__device__ __align__(16) int   g_cur [N_NODES];      // running cursors for counting sort
__device__ int   g_vedge[NNZ];                       // edge id per incidence, by vertex
__device__ int   g_start[N_EDGES + 1];               // CSR bounds of sorted `edges`
__device__ int   g_bsum[NB_SCAN];                    // per-chunk sums for scan
__device__ float g_M1[D * D];                        // W2a @ W_w
__device__ float g_M2[D * D];                        // W2b @ W_w
__device__ float g_c1[D];                            // W2_b @ W_w

// ---------------- init: zero counters + fold small matrices ----------------
__global__ void k_init(const float* __restrict__ W2w,
                       const float* __restrict__ W2b,
                       const float* __restrict__ Ww) {
    int tid = blockIdx.x * blockDim.x + threadIdx.x;
    int stride = gridDim.x * blockDim.x;
    const int total = N_NODES + (N_EDGES + 1);
    for (int i = tid; i < total; i += stride) {
        if (i < N_NODES) g_deg[i] = 0;
        else             g_start[i - N_NODES] = NNZ;
    }
    if (tid < D * D) {
        int k = tid >> 5, j = tid & 31;
        float s1 = 0.f, s2 = 0.f;
        #pragma unroll
        for (int m = 0; m < D; m++) {
            s1 = fmaf(W2w[k * D + m],       Ww[m * D + j], s1);
            s2 = fmaf(W2w[(D + k) * D + m], Ww[m * D + j], s2);
        }
        g_M1[tid] = s1;
        g_M2[tid] = s2;
        if (k == 0) {
            float c = 0.f;
            #pragma unroll
            for (int m = 0; m < D; m++) c = fmaf(W2b[m], Ww[m * D + j], c);
            g_c1[j] = c;
        }
    }
}

// ---------------- edge segment bounds (edges is sorted ascending) ----------------
__global__ void k_fill(const int* __restrict__ edges) {
    int tid = blockIdx.x * blockDim.x + threadIdx.x;
    int stride = gridDim.x * blockDim.x;
    const int nv = NNZ / 4;
    for (int q = tid; q < nv; q += stride) {
        int4 e4 = reinterpret_cast<const int4*>(edges)[q];
        int i = q * 4;
        int p = (i == 0) ? -1 : __ldg(&edges[i - 1]);
        if (e4.x != p)    for (int k = p + 1;    k <= e4.x; k++) g_start[k] = i;
        if (e4.y != e4.x) for (int k = e4.x + 1; k <= e4.y; k++) g_start[k] = i + 1;
        if (e4.z != e4.y) for (int k = e4.y + 1; k <= e4.z; k++) g_start[k] = i + 2;
        if (e4.w != e4.z) for (int k = e4.z + 1; k <= e4.w; k++) g_start[k] = i + 3;
    }
}

// ---------------- vertex degree histogram ----------------
__global__ void k_deg(const int* __restrict__ vertex) {
    int tid = blockIdx.x * blockDim.x + threadIdx.x;
    int stride = gridDim.x * blockDim.x;
    const int nv = NNZ / 4;
    for (int q = tid; q < nv; q += stride) {
        int4 v4 = reinterpret_cast<const int4*>(vertex)[q];
        atomicAdd(&g_deg[v4.x], 1);
        atomicAdd(&g_deg[v4.y], 1);
        atomicAdd(&g_deg[v4.z], 1);
        atomicAdd(&g_deg[v4.w], 1);
    }
}

// ---------------- 3-phase multi-block exclusive scan of g_deg -> g_voff/g_cur ----
__global__ void k_scan1() {
    __shared__ int wsum[8];
    int t = threadIdx.x, b = blockIdx.x;
    int gi = b * 256 + t;
    int s = 0;
    if (gi < N4) {
        int4 d = reinterpret_cast<const int4*>(g_deg)[gi];
        s = d.x + d.y + d.z + d.w;
    }
    #pragma unroll
    for (int off = 16; off > 0; off >>= 1)
        s += __shfl_down_sync(0xffffffffu, s, off);
    if ((t & 31) == 0) wsum[t >> 5] = s;
    __syncthreads();
    if (t == 0) {
        int r = 0;
        #pragma unroll
        for (int w = 0; w < 8; w++) r += wsum[w];
        g_bsum[b] = r;
    }
}

__global__ void k_scan2() {
    __shared__ int ssum[128];
    int t = threadIdx.x;
    ssum[t] = (t < NB_SCAN) ? g_bsum[t] : 0;
    __syncthreads();
    #pragma unroll
    for (int off = 1; off < 128; off <<= 1) {
        int v = (t >= off) ? ssum[t - off] : 0;
        __syncthreads();
        ssum[t] += v;
        __syncthreads();
    }
    if (t < NB_SCAN) g_bsum[t] = (t > 0) ? ssum[t - 1] : 0;
    if (t == 0) g_voff[N_NODES] = NNZ;
}

__global__ void k_scan3() {
    __shared__ int wsum[8];
    __shared__ int wbase[8];
    int t = threadIdx.x, b = blockIdx.x;
    int lane = t & 31, wid = t >> 5;
    int gi = b * 256 + t;

    int4 d = make_int4(0, 0, 0, 0);
    if (gi < N4) d = reinterpret_cast<const int4*>(g_deg)[gi];
    int s = d.x + d.y + d.z + d.w;

    int ws = s;
    #pragma unroll
    for (int off = 1; off < 32; off <<= 1) {
        int n = __shfl_up_sync(0xffffffffu, ws, off);
        if (lane >= off) ws += n;
    }
    if (lane == 31) wsum[wid] = ws;
    __syncthreads();
    if (t == 0) {
        int r = 0;
        #pragma unroll
        for (int w = 0; w < 8; w++) { wbase[w] = r; r += wsum[w]; }
    }
    __syncthreads();

    if (gi < N4) {
        int e0 = g_bsum[b] + wbase[wid] + (ws - s);
        int4 o = make_int4(e0, e0 + d.x, e0 + d.x + d.y, e0 + d.x + d.y + d.z);
        reinterpret_cast<int4*>(g_voff)[gi] = o;
        reinterpret_cast<int4*>(g_cur )[gi] = o;
    }
}

// ---------------- counting sort: group incidence edge-ids by vertex ----------------
__global__ void k_sidx(const int* __restrict__ vertex,
                       const int* __restrict__ edges) {
    int tid = blockIdx.x * blockDim.x + threadIdx.x;
    int stride = gridDim.x * blockDim.x;
    const int nv = NNZ / 4;
    for (int q = tid; q < nv; q += stride) {
        int4 v4 = reinterpret_cast<const int4*>(vertex)[q];
        int4 e4 = reinterpret_cast<const int4*>(edges)[q];
        g_vedge[atomicAdd(&g_cur[v4.x], 1)] = e4.x;
        g_vedge[atomicAdd(&g_cur[v4.y], 1)] = e4.y;
        g_vedge[atomicAdd(&g_cur[v4.z], 1)] = e4.z;
        g_vedge[atomicAdd(&g_cur[v4.w], 1)] = e4.w;
    }
}

// ---------------- thread-per-node register matvecs ----------------
__global__ void __launch_bounds__(256) k_pre(
        const float* __restrict__ X,
        const float* __restrict__ X0,
        const float* __restrict__ W1w,
        const float* __restrict__ W1b,
        const float* __restrict__ Ww,
        const float* __restrict__ Wb) {
    __shared__ float sW1[D * D], sM1[D * D], sW[D * D];
    __shared__ float sb1[D], sc1[D], sWb[D];
    int t = threadIdx.x;
    for (int i = t; i < D * D; i += blockDim.x) {
        sW1[i] = W1w[i];
        sM1[i] = g_M1[i];
        sW [i] = Ww[i];
    }
    if (t < D) { sb1[t] = W1b[t]; sc1[t] = g_c1[t]; sWb[t] = Wb[t]; }
    __syncthreads();

    int v = blockIdx.x * blockDim.x + t;
    if (v >= N_NODES) return;

    float x[D];
    const float4* Xr = reinterpret_cast<const float4*>(X) + v * (D / 4);
    #pragma unroll
    for (int i = 0; i < D / 4; i++) {
        float4 q = __ldg(&Xr[i]);
        x[4*i] = q.x; x[4*i+1] = q.y; x[4*i+2] = q.z; x[4*i+3] = q.w;
    }

    float acc[D];
    #pragma unroll
    for (int j = 0; j < D; j++) acc[j] = sb1[j];
    #pragma unroll
    for (int k = 0; k < D; k++) {
        float xk = x[k];
        #pragma unroll
        for (int j = 0; j < D; j++) acc[j] = fmaf(xk, sW1[k * D + j], acc[j]);
    }
    float4* X1r = reinterpret_cast<float4*>(g_X1) + v * (D / 4);
    #pragma unroll
    for (int i = 0; i < D / 4; i++)
        X1r[i] = make_float4(acc[4*i], acc[4*i+1], acc[4*i+2], acc[4*i+3]);

    float degf = __int2float_rn(g_deg[v]);
    float sc = OMA * degf;
    #pragma unroll
    for (int j = 0; j < D; j++) acc[j] = sc1[j];
    #pragma unroll
    for (int k = 0; k < D; k++) {
        float xk = x[k];
        #pragma unroll
        for (int j = 0; j < D; j++) acc[j] = fmaf(xk, sM1[k * D + j], acc[j]);
    }
    #pragma unroll
    for (int j = 0; j < D; j++)
        acc[j] = (fmaf(sc, acc[j], sWb[j])) * (1.0f / ALPHA);

    const float4* X0r = reinterpret_cast<const float4*>(X0) + v * (D / 4);
    #pragma unroll
    for (int i = 0; i < D / 4; i++) {
        float4 q = __ldg(&X0r[i]);
        x[4*i] = q.x; x[4*i+1] = q.y; x[4*i+2] = q.z; x[4*i+3] = q.w;
    }
    #pragma unroll
    for (int k = 0; k < D; k++) {
        float xk = x[k];
        #pragma unroll
        for (int j = 0; j < D; j++) acc[j] = fmaf(xk, sW[k * D + j], acc[j]);
    }
    float4* Tr = reinterpret_cast<float4*>(g_T) + v * (D / 4);
    #pragma unroll
    for (int i = 0; i < D / 4; i++)
        Tr[i] = make_float4(ALPHA * acc[4*i], ALPHA * acc[4*i+1],
                            ALPHA * acc[4*i+2], ALPHA * acc[4*i+3]);
}

// ---------------- warp-per-edge, 4 rows/step via float4 lanes:
//   Xe = sum(atts * X1[vertex]); Ye = Xe @ M2 ----------------
__global__ void k_xe(const int* __restrict__ vertex,
                     const float* __restrict__ atts) {
    __shared__ float sM2[D * D];
    int t = threadIdx.x;
    for (int i = t; i < D * D; i += blockDim.x) sM2[i] = g_M2[i];
    __syncthreads();

    int lane = t & 31;
    int cg  = lane & 7;      // column group: floats [4cg, 4cg+3]
    int sub = lane >> 3;     // which of 4 rows per step
    int warp = (blockIdx.x * blockDim.x + t) >> 5;
    int nwarps = (gridDim.x * blockDim.x) >> 5;

    for (int e = warp; e < N_EDGES; e += nwarps) {
        int s = g_start[e];
        int tEnd = g_start[e + 1];

        float4 acc = make_float4(0.f, 0.f, 0.f, 0.f);
        for (int base = s; base < tEnd; base += 32) {
            int n = tEnd - base; if (n > 32) n = 32;
            int vi = 0; float ai = 0.f;
            if (lane < n) {
                vi = __ldg(&vertex[base + lane]);
                ai = __ldg(&atts[base + lane]);
            }
            for (int j = 0; j < n; j += 4) {
                int r = j + sub;                 // shfl wraps mod 32; guarded below
                int   v = __shfl_sync(0xffffffffu, vi, r);
                float a = __shfl_sync(0xffffffffu, ai, r);
                if (r < n) {
                    float4 xr = *reinterpret_cast<const float4*>(&g_X1[v * D + cg * 4]);
                    acc.x = fmaf(a, xr.x, acc.x);
                    acc.y = fmaf(a, xr.y, acc.y);
                    acc.z = fmaf(a, xr.z, acc.z);
                    acc.w = fmaf(a, xr.w, acc.w);
                }
            }
        }
        // butterfly-reduce the 4 sub-rows (bits 3 and 4 of lane)
        #pragma unroll
        for (int off = 8; off <= 16; off <<= 1) {
            acc.x += __shfl_xor_sync(0xffffffffu, acc.x, off);
            acc.y += __shfl_xor_sync(0xffffffffu, acc.y, off);
            acc.z += __shfl_xor_sync(0xffffffffu, acc.z, off);
            acc.w += __shfl_xor_sync(0xffffffffu, acc.w, off);
        }
        // Ye = Xe @ M2 : x_k lives in lane (k>>2), component (k&3)
        float y = 0.f;
        #pragma unroll
        for (int q = 0; q < 8; q++) {
            float x0 = __shfl_sync(0xffffffffu, acc.x, q);
            float x1 = __shfl_sync(0xffffffffu, acc.y, q);
            float x2 = __shfl_sync(0xffffffffu, acc.z, q);
            float x3 = __shfl_sync(0xffffffffu, acc.w, q);
            y = fmaf(x0, sM2[(4*q + 0) * D + lane], y);
            y = fmaf(x1, sM2[(4*q + 1) * D + lane], y);
            y = fmaf(x2, sM2[(4*q + 2) * D + lane], y);
            y = fmaf(x3, sM2[(4*q + 3) * D + lane], y);
        }
        g_Ye[e * D + lane] = y;
    }
}

// ---------------- warp-per-vertex, 4 rows/step: out = T + (1-a)*sum(Ye[inc]) ----
__global__ void k_gout(float* __restrict__ out) {
    int t = threadIdx.x;
    int lane = t & 31;
    int cg  = lane & 7;
    int sub = lane >> 3;
    int warp = (blockIdx.x * blockDim.x + t) >> 5;
    int nwarps = (gridDim.x * blockDim.x) >> 5;

    for (int v = warp; v < N_NODES; v += nwarps) {
        int s = g_voff[v];
        int e2 = g_voff[v + 1];

        float4 acc = make_float4(0.f, 0.f, 0.f, 0.f);
        for (int base = s; base < e2; base += 32) {
            int n = e2 - base; if (n > 32) n = 32;
            int ei = 0;
            if (lane < n) ei = __ldg(&g_vedge[base + lane]);
            for (int j = 0; j < n; j += 4) {
                int r = j + sub;
                int ee = __shfl_sync(0xffffffffu, ei, r);
                if (r < n) {
                    float4 yr = *reinterpret_cast<const float4*>(&g_Ye[ee * D + cg * 4]);
                    acc.x += yr.x; acc.y += yr.y; acc.z += yr.z; acc.w += yr.w;
                }
            }
        }
        #pragma unroll
        for (int off = 8; off <= 16; off <<= 1) {
            acc.x += __shfl_xor_sync(0xffffffffu, acc.x, off);
            acc.y += __shfl_xor_sync(0xffffffffu, acc.y, off);
            acc.z += __shfl_xor_sync(0xffffffffu, acc.z, off);
            acc.w += __shfl_xor_sync(0xffffffffu, acc.w, off);
        }
        if (sub == 0) {  // lanes 0..7 write the 32-float row as 8 float4s
            float4 tv = *reinterpret_cast<const float4*>(&g_T[v * D + cg * 4]);
            float4 o;
            o.x = fmaf(OMA, acc.x, tv.x);
            o.y = fmaf(OMA, acc.y, tv.y);
            o.z = fmaf(OMA, acc.z, tv.z);
            o.w = fmaf(OMA, acc.w, tv.w);
            *reinterpret_cast<float4*>(&out[v * D + cg * 4]) = o;
        }
    }
}

// ---------------- launch ----------------
extern "C" void kernel_launch(void* const* d_in, const int* in_sizes, int n_in,
                              void* d_out, int out_size) {
    const float* X    = (const float*)d_in[0];
    const float* X0   = (const float*)d_in[1];
    const float* atts = (const float*)d_in[2];
    const float* W1w  = (const float*)d_in[3];
    const float* W1b  = (const float*)d_in[4];
    const float* W2w  = (const float*)d_in[5];
    const float* W2b  = (const float*)d_in[6];
    const float* Ww   = (const float*)d_in[7];
    const float* Wb   = (const float*)d_in[8];
    const int* vertex = (const int*)d_in[9];
    const int* edges  = (const int*)d_in[10];
    float* out = (float*)d_out;

    k_init <<<512, 256>>>(W2w, W2b, Ww);
    k_fill <<<1024, 256>>>(edges);
    k_deg  <<<1024, 256>>>(vertex);
    k_scan1<<<NB_SCAN, 256>>>();
    k_scan2<<<1, 128>>>();
    k_scan3<<<NB_SCAN, 256>>>();
    k_sidx <<<1024, 256>>>(vertex, edges);
    k_pre  <<<(N_NODES + 255) / 256, 256>>>(X, X0, W1w, W1b, Ww, Wb);
    k_xe   <<<6250, 256>>>(vertex, atts);    // 50k warps = 1 warp / hyperedge
    k_gout <<<12500, 256>>>(out);            // 100k warps = 1 warp / vertex
}

// round 10
// speedup vs baseline: 2.1829x; 1.1392x over previous
#include <cuda_runtime.h>
#include <cuda_fp16.h>

#define N_NODES 100000
#define N_EDGES 50000
#define NNZ     3200000
#define D       32
#define ALPHA   0.5f
#define OMA     0.5f   /* 1 - ALPHA */

#define N4       (N_NODES / 4)                 /* 25000 int4 */
#define NB_SCAN  ((N4 + 255) / 256)            /* 98 blocks */

// ---------------- device scratch (no allocs allowed) ----------------
__device__ __align__(256) __half g_X1h[N_NODES * D]; // X @ W1 + b1  (fp16, 6.4MB)
__device__ __align__(256) __half g_Yeh[N_EDGES * D]; // Xe @ M2     (fp16, 3.2MB)
__device__ __align__(256) float  g_T  [N_NODES * D]; // node closed-form part (fp32)
__device__ __align__(16) int   g_deg [N_NODES];      // incidence count per vertex
__device__ __align__(16) int   g_voff[N_NODES + 4];  // CSR offsets by vertex
__device__ __align__(16) int   g_cur [N_NODES];      // counting-sort cursors
__device__ int   g_vedge[NNZ];                       // edge id per incidence, by vertex
__device__ int   g_start[N_EDGES + 1];               // CSR bounds of sorted `edges`
__device__ int   g_bsum[NB_SCAN];                    // per-chunk sums for scan
__device__ float g_M1[D * D];                        // W2a @ W_w
__device__ float g_M2[D * D];                        // W2b @ W_w
__device__ float g_c1[D];                            // W2_b @ W_w

// ---------------- init: zero counters + fold small matrices ----------------
__global__ void k_init(const float* __restrict__ W2w,
                       const float* __restrict__ W2b,
                       const float* __restrict__ Ww) {
    int tid = blockIdx.x * blockDim.x + threadIdx.x;
    int stride = gridDim.x * blockDim.x;
    const int total = N_NODES + (N_EDGES + 1);
    for (int i = tid; i < total; i += stride) {
        if (i < N_NODES) g_deg[i] = 0;
        else             g_start[i - N_NODES] = NNZ;
    }
    if (tid < D * D) {
        int k = tid >> 5, j = tid & 31;
        float s1 = 0.f, s2 = 0.f;
        #pragma unroll
        for (int m = 0; m < D; m++) {
            s1 = fmaf(W2w[k * D + m],       Ww[m * D + j], s1);
            s2 = fmaf(W2w[(D + k) * D + m], Ww[m * D + j], s2);
        }
        g_M1[tid] = s1;
        g_M2[tid] = s2;
        if (k == 0) {
            float c = 0.f;
            #pragma unroll
            for (int m = 0; m < D; m++) c = fmaf(W2b[m], Ww[m * D + j], c);
            g_c1[j] = c;
        }
    }
}

// ---------------- fused: vertex degree histogram + edge segment bounds ----------
__global__ void k_degfill(const int* __restrict__ vertex,
                          const int* __restrict__ edges) {
    int tid = blockIdx.x * blockDim.x + threadIdx.x;
    int stride = gridDim.x * blockDim.x;
    const int nv = NNZ / 4;
    for (int q = tid; q < nv; q += stride) {
        int4 v4 = reinterpret_cast<const int4*>(vertex)[q];
        atomicAdd(&g_deg[v4.x], 1);
        atomicAdd(&g_deg[v4.y], 1);
        atomicAdd(&g_deg[v4.z], 1);
        atomicAdd(&g_deg[v4.w], 1);

        int4 e4 = reinterpret_cast<const int4*>(edges)[q];
        int i = q * 4;
        int p = (i == 0) ? -1 : __ldg(&edges[i - 1]);
        if (e4.x != p)    for (int k = p + 1;    k <= e4.x; k++) g_start[k] = i;
        if (e4.y != e4.x) for (int k = e4.x + 1; k <= e4.y; k++) g_start[k] = i + 1;
        if (e4.z != e4.y) for (int k = e4.y + 1; k <= e4.z; k++) g_start[k] = i + 2;
        if (e4.w != e4.z) for (int k = e4.z + 1; k <= e4.w; k++) g_start[k] = i + 3;
    }
}

// ---------------- thread-per-node register matvecs ----------------
__global__ void __launch_bounds__(256) k_pre(
        const float* __restrict__ X,
        const float* __restrict__ X0,
        const float* __restrict__ W1w,
        const float* __restrict__ W1b,
        const float* __restrict__ Ww,
        const float* __restrict__ Wb) {
    __shared__ float sW1[D * D], sM1[D * D], sW[D * D];
    __shared__ float sb1[D], sc1[D], sWb[D];
    int t = threadIdx.x;
    for (int i = t; i < D * D; i += blockDim.x) {
        sW1[i] = W1w[i];
        sM1[i] = g_M1[i];
        sW [i] = Ww[i];
    }
    if (t < D) { sb1[t] = W1b[t]; sc1[t] = g_c1[t]; sWb[t] = Wb[t]; }
    __syncthreads();

    int v = blockIdx.x * blockDim.x + t;
    if (v >= N_NODES) return;

    float x[D];
    const float4* Xr = reinterpret_cast<const float4*>(X) + v * (D / 4);
    #pragma unroll
    for (int i = 0; i < D / 4; i++) {
        float4 q = __ldg(&Xr[i]);
        x[4*i] = q.x; x[4*i+1] = q.y; x[4*i+2] = q.z; x[4*i+3] = q.w;
    }

    float acc[D];
    // phase 1: X1 = x @ W1 + b1 -> fp16
    #pragma unroll
    for (int j = 0; j < D; j++) acc[j] = sb1[j];
    #pragma unroll
    for (int k = 0; k < D; k++) {
        float xk = x[k];
        #pragma unroll
        for (int j = 0; j < D; j++) acc[j] = fmaf(xk, sW1[k * D + j], acc[j]);
    }
    __half2* X1r = reinterpret_cast<__half2*>(g_X1h) + v * (D / 2);
    #pragma unroll
    for (int i = 0; i < D / 2; i++)
        X1r[i] = __floats2half2_rn(acc[2*i], acc[2*i+1]);

    // phase 2: m = x @ M1 + c1 ; acc := (OMA*deg*m + Wb) / ALPHA
    float degf = __int2float_rn(g_deg[v]);
    float sc = OMA * degf;
    #pragma unroll
    for (int j = 0; j < D; j++) acc[j] = sc1[j];
    #pragma unroll
    for (int k = 0; k < D; k++) {
        float xk = x[k];
        #pragma unroll
        for (int j = 0; j < D; j++) acc[j] = fmaf(xk, sM1[k * D + j], acc[j]);
    }
    #pragma unroll
    for (int j = 0; j < D; j++)
        acc[j] = (fmaf(sc, acc[j], sWb[j])) * (1.0f / ALPHA);

    // phase 3: acc += X0 @ Ww ; T = ALPHA * acc
    const float4* X0r = reinterpret_cast<const float4*>(X0) + v * (D / 4);
    #pragma unroll
    for (int i = 0; i < D / 4; i++) {
        float4 q = __ldg(&X0r[i]);
        x[4*i] = q.x; x[4*i+1] = q.y; x[4*i+2] = q.z; x[4*i+3] = q.w;
    }
    #pragma unroll
    for (int k = 0; k < D; k++) {
        float xk = x[k];
        #pragma unroll
        for (int j = 0; j < D; j++) acc[j] = fmaf(xk, sW[k * D + j], acc[j]);
    }
    float4* Tr = reinterpret_cast<float4*>(g_T) + v * (D / 4);
    #pragma unroll
    for (int i = 0; i < D / 4; i++)
        Tr[i] = make_float4(ALPHA * acc[4*i], ALPHA * acc[4*i+1],
                            ALPHA * acc[4*i+2], ALPHA * acc[4*i+3]);
}

// ---------------- warp-per-edge, 8 rows/step via fp16 uint4 lanes:
//   Xe = sum(atts * X1[vertex]); Ye = Xe @ M2 -> fp16 ----------------
__global__ void k_xe(const int* __restrict__ vertex,
                     const float* __restrict__ atts) {
    __shared__ float sM2[D * D];
    int t = threadIdx.x;
    for (int i = t; i < D * D; i += blockDim.x) sM2[i] = g_M2[i];
    __syncthreads();

    int lane = t & 31;
    int cq  = lane & 3;      // column quarter: halfs [8cq, 8cq+7]
    int sub = lane >> 2;     // which of 8 rows per step
    int warp = (blockIdx.x * blockDim.x + t) >> 5;
    int nwarps = (gridDim.x * blockDim.x) >> 5;

    const uint4* Xh = reinterpret_cast<const uint4*>(g_X1h);  // 4 uint4 per row

    for (int e = warp; e < N_EDGES; e += nwarps) {
        int s = g_start[e];
        int tEnd = g_start[e + 1];

        float acc[8];
        #pragma unroll
        for (int c = 0; c < 8; c++) acc[c] = 0.f;

        for (int base = s; base < tEnd; base += 32) {
            int n = tEnd - base; if (n > 32) n = 32;
            int vi = 0; float ai = 0.f;
            if (lane < n) {
                vi = __ldg(&vertex[base + lane]);
                ai = __ldg(&atts[base + lane]);
            }
            for (int j = 0; j < n; j += 8) {
                int r = j + sub;                 // r <= 31 always
                int   v = __shfl_sync(0xffffffffu, vi, r);
                float a = __shfl_sync(0xffffffffu, ai, r);
                if (r < n) {
                    uint4 h = Xh[v * 4 + cq];
                    float2 f0 = __half22float2(*reinterpret_cast<__half2*>(&h.x));
                    float2 f1 = __half22float2(*reinterpret_cast<__half2*>(&h.y));
                    float2 f2 = __half22float2(*reinterpret_cast<__half2*>(&h.z));
                    float2 f3 = __half22float2(*reinterpret_cast<__half2*>(&h.w));
                    acc[0] = fmaf(a, f0.x, acc[0]); acc[1] = fmaf(a, f0.y, acc[1]);
                    acc[2] = fmaf(a, f1.x, acc[2]); acc[3] = fmaf(a, f1.y, acc[3]);
                    acc[4] = fmaf(a, f2.x, acc[4]); acc[5] = fmaf(a, f2.y, acc[5]);
                    acc[6] = fmaf(a, f3.x, acc[6]); acc[7] = fmaf(a, f3.y, acc[7]);
                }
            }
        }
        // reduce the 8 sub-rows (lane bits 2,3,4)
        #pragma unroll
        for (int off = 4; off <= 16; off <<= 1) {
            #pragma unroll
            for (int c = 0; c < 8; c++)
                acc[c] += __shfl_xor_sync(0xffffffffu, acc[c], off);
        }
        // Ye = Xe @ M2 : component k lives in lane (k>>3), slot (k&7)
        float y = 0.f;
        #pragma unroll
        for (int q = 0; q < 4; q++) {
            #pragma unroll
            for (int c = 0; c < 8; c++) {
                float xk = __shfl_sync(0xffffffffu, acc[c], q);
                y = fmaf(xk, sM2[(q * 8 + c) * D + lane], y);
            }
        }
        g_Yeh[e * D + lane] = __float2half(y);
    }
}

// ---------------- 3-phase multi-block exclusive scan of g_deg -> g_voff/g_cur ----
__global__ void k_scan1() {
    __shared__ int wsum[8];
    int t = threadIdx.x, b = blockIdx.x;
    int gi = b * 256 + t;
    int s = 0;
    if (gi < N4) {
        int4 d = reinterpret_cast<const int4*>(g_deg)[gi];
        s = d.x + d.y + d.z + d.w;
    }
    #pragma unroll
    for (int off = 16; off > 0; off >>= 1)
        s += __shfl_down_sync(0xffffffffu, s, off);
    if ((t & 31) == 0) wsum[t >> 5] = s;
    __syncthreads();
    if (t == 0) {
        int r = 0;
        #pragma unroll
        for (int w = 0; w < 8; w++) r += wsum[w];
        g_bsum[b] = r;
    }
}

__global__ void k_scan2() {
    __shared__ int ssum[128];
    int t = threadIdx.x;
    ssum[t] = (t < NB_SCAN) ? g_bsum[t] : 0;
    __syncthreads();
    #pragma unroll
    for (int off = 1; off < 128; off <<= 1) {
        int v = (t >= off) ? ssum[t - off] : 0;
        __syncthreads();
        ssum[t] += v;
        __syncthreads();
    }
    if (t < NB_SCAN) g_bsum[t] = (t > 0) ? ssum[t - 1] : 0;
    if (t == 0) g_voff[N_NODES] = NNZ;
}

__global__ void k_scan3() {
    __shared__ int wsum[8];
    __shared__ int wbase[8];
    int t = threadIdx.x, b = blockIdx.x;
    int lane = t & 31, wid = t >> 5;
    int gi = b * 256 + t;

    int4 d = make_int4(0, 0, 0, 0);
    if (gi < N4) d = reinterpret_cast<const int4*>(g_deg)[gi];
    int s = d.x + d.y + d.z + d.w;

    int ws = s;
    #pragma unroll
    for (int off = 1; off < 32; off <<= 1) {
        int n = __shfl_up_sync(0xffffffffu, ws, off);
        if (lane >= off) ws += n;
    }
    if (lane == 31) wsum[wid] = ws;
    __syncthreads();
    if (t == 0) {
        int r = 0;
        #pragma unroll
        for (int w = 0; w < 8; w++) { wbase[w] = r; r += wsum[w]; }
    }
    __syncthreads();

    if (gi < N4) {
        int e0 = g_bsum[b] + wbase[wid] + (ws - s);
        int4 o = make_int4(e0, e0 + d.x, e0 + d.x + d.y, e0 + d.x + d.y + d.z);
        reinterpret_cast<int4*>(g_voff)[gi] = o;
        reinterpret_cast<int4*>(g_cur )[gi] = o;
    }
}

// ---------------- counting sort: group incidence edge-ids by vertex ----------------
__global__ void k_sidx(const int* __restrict__ vertex,
                       const int* __restrict__ edges) {
    int tid = blockIdx.x * blockDim.x + threadIdx.x;
    int stride = gridDim.x * blockDim.x;
    const int nv = NNZ / 4;
    for (int q = tid; q < nv; q += stride) {
        int4 v4 = reinterpret_cast<const int4*>(vertex)[q];
        int4 e4 = reinterpret_cast<const int4*>(edges)[q];
        g_vedge[atomicAdd(&g_cur[v4.x], 1)] = e4.x;
        g_vedge[atomicAdd(&g_cur[v4.y], 1)] = e4.y;
        g_vedge[atomicAdd(&g_cur[v4.z], 1)] = e4.z;
        g_vedge[atomicAdd(&g_cur[v4.w], 1)] = e4.w;
    }
}

// ---------------- warp-per-vertex, 8 rows/step: out = T + (1-a)*sum(Ye[inc]) ----
__global__ void k_gout(float* __restrict__ out) {
    int t = threadIdx.x;
    int lane = t & 31;
    int cq  = lane & 3;
    int sub = lane >> 2;
    int warp = (blockIdx.x * blockDim.x + t) >> 5;
    int nwarps = (gridDim.x * blockDim.x) >> 5;

    const uint4* Yh = reinterpret_cast<const uint4*>(g_Yeh);  // 4 uint4 per row

    for (int v = warp; v < N_NODES; v += nwarps) {
        int s = g_voff[v];
        int e2 = g_voff[v + 1];

        float acc[8];
        #pragma unroll
        for (int c = 0; c < 8; c++) acc[c] = 0.f;

        for (int base = s; base < e2; base += 32) {
            int n = e2 - base; if (n > 32) n = 32;
            int ei = 0;
            if (lane < n) ei = __ldg(&g_vedge[base + lane]);
            for (int j = 0; j < n; j += 8) {
                int r = j + sub;
                int ee = __shfl_sync(0xffffffffu, ei, r);
                if (r < n) {
                    uint4 h = Yh[ee * 4 + cq];
                    float2 f0 = __half22float2(*reinterpret_cast<__half2*>(&h.x));
                    float2 f1 = __half22float2(*reinterpret_cast<__half2*>(&h.y));
                    float2 f2 = __half22float2(*reinterpret_cast<__half2*>(&h.z));
                    float2 f3 = __half22float2(*reinterpret_cast<__half2*>(&h.w));
                    acc[0] += f0.x; acc[1] += f0.y;
                    acc[2] += f1.x; acc[3] += f1.y;
                    acc[4] += f2.x; acc[5] += f2.y;
                    acc[6] += f3.x; acc[7] += f3.y;
                }
            }
        }
        #pragma unroll
        for (int off = 4; off <= 16; off <<= 1) {
            #pragma unroll
            for (int c = 0; c < 8; c++)
                acc[c] += __shfl_xor_sync(0xffffffffu, acc[c], off);
        }
        if (sub == 0) {  // lanes 0..3 write 8 floats each (2 float4s)
            const float4* Tr = reinterpret_cast<const float4*>(g_T) + v * 8 + cq * 2;
            float4 t0 = Tr[0], t1 = Tr[1];
            float4 o0, o1;
            o0.x = fmaf(OMA, acc[0], t0.x); o0.y = fmaf(OMA, acc[1], t0.y);
            o0.z = fmaf(OMA, acc[2], t0.z); o0.w = fmaf(OMA, acc[3], t0.w);
            o1.x = fmaf(OMA, acc[4], t1.x); o1.y = fmaf(OMA, acc[5], t1.y);
            o1.z = fmaf(OMA, acc[6], t1.z); o1.w = fmaf(OMA, acc[7], t1.w);
            float4* Or = reinterpret_cast<float4*>(out) + v * 8 + cq * 2;
            Or[0] = o0; Or[1] = o1;
        }
    }
}

// ---------------- launch ----------------
extern "C" void kernel_launch(void* const* d_in, const int* in_sizes, int n_in,
                              void* d_out, int out_size) {
    const float* X    = (const float*)d_in[0];
    const float* X0   = (const float*)d_in[1];
    const float* atts = (const float*)d_in[2];
    const float* W1w  = (const float*)d_in[3];
    const float* W1b  = (const float*)d_in[4];
    const float* W2w  = (const float*)d_in[5];
    const float* W2b  = (const float*)d_in[6];
    const float* Ww   = (const float*)d_in[7];
    const float* Wb   = (const float*)d_in[8];
    const int* vertex = (const int*)d_in[9];
    const int* edges  = (const int*)d_in[10];
    float* out = (float*)d_out;

    // order chosen so launch index 3 (the profiled one) is k_xe
    k_init   <<<512, 256>>>(W2w, W2b, Ww);                      // 0
    k_degfill<<<1024, 256>>>(vertex, edges);                    // 1
    k_pre    <<<(N_NODES + 255) / 256, 256>>>(X, X0, W1w, W1b, Ww, Wb); // 2
    k_xe     <<<6250, 256>>>(vertex, atts);                     // 3  <- profiled
    k_scan1  <<<NB_SCAN, 256>>>();                              // 4
    k_scan2  <<<1, 128>>>();                                    // 5
    k_scan3  <<<NB_SCAN, 256>>>();                              // 6
    k_sidx   <<<1024, 256>>>(vertex, edges);                    // 7
    k_gout   <<<12500, 256>>>(out);                             // 8
}